// round 11
// baseline (speedup 1.0000x reference)
#include <cuda_runtime.h>
#include <float.h>
#include <math.h>

#define FULLMASK 0xffffffffu

typedef unsigned long long ull;

static const int NN = 20000;   // nodes
static const int NE = 640000;  // edges
static const int NG = 64;      // graphs

// ---------------- packed f32x2 helpers ---------------------------------------
__device__ __forceinline__ ull pack2(float x, float y) {
    ull r; asm("mov.b64 %0,{%1,%2};" : "=l"(r) : "f"(x), "f"(y)); return r;
}
__device__ __forceinline__ ull dup2(float x) { return pack2(x, x); }
__device__ __forceinline__ void unpack2(ull v, float& x, float& y) {
    asm("mov.b64 {%0,%1},%2;" : "=f"(x), "=f"(y) : "l"(v));
}
__device__ __forceinline__ void fma2(ull& d, ull a, ull b) {
    asm("fma.rn.f32x2 %0,%1,%2,%0;" : "+l"(d) : "l"(a), "l"(b));
}
__device__ __forceinline__ ull add2(ull a, ull b) {
    ull r; asm("add.rn.f32x2 %0,%1,%2;" : "=l"(r) : "l"(a), "l"(b)); return r;
}
__device__ __forceinline__ ull mul2(ull a, ull b) {
    ull r; asm("mul.rn.f32x2 %0,%1,%2;" : "=l"(r) : "l"(a), "l"(b)); return r;
}

// ---------------- tf32 helpers ----------------------------------------------
__device__ __forceinline__ unsigned f2tf(float x) {
    unsigned r; asm("cvt.rna.tf32.f32 %0,%1;" : "=r"(r) : "f"(x)); return r;
}
__device__ __forceinline__ void mma_tf32(float* c, const unsigned* a, const unsigned* b) {
    asm volatile(
        "mma.sync.aligned.m16n8k8.row.col.f32.tf32.tf32.f32 "
        "{%0,%1,%2,%3},{%4,%5,%6,%7},{%8,%9},{%0,%1,%2,%3};"
        : "+f"(c[0]), "+f"(c[1]), "+f"(c[2]), "+f"(c[3])
        : "r"(a[0]), "r"(a[1]), "r"(a[2]), "r"(a[3]), "r"(b[0]), "r"(b[1]));
}

// ---------------- scratch ----------------------------------------------------
__device__ float g_XL[20000 * 512];
__device__ float g_XR[20000 * 512];
__device__ float g_HA[20000 * 256];
__device__ float g_HB[20000 * 256];
__device__ int   g_cnt[20000];
__device__ int   g_rowptr[20001];
__device__ int   g_cursor[20000];
__device__ int   g_csrc[640000];
__device__ int   g_ceid[640000];
__device__ __align__(16) float g_eacsr[640000 * 16];
__device__ int   g_gcnt[64];

// ---------------- CSR build --------------------------------------------------
__global__ void k_zero_cnt(int* cnt, int n) {
    int i = blockIdx.x * blockDim.x + threadIdx.x;
    if (i < n) cnt[i] = 0;
}

__global__ void k_hist(const int* __restrict__ ei, int* cnt, int E) {
    int e = blockIdx.x * blockDim.x + threadIdx.x;
    if (e < E) atomicAdd(&cnt[ei[E + e]], 1);
}

__global__ void k_scan(const int* __restrict__ cnt, int* rowptr, int* cursor, int n) {
    __shared__ int wsum[32];
    __shared__ int carry_s;
    int tid = threadIdx.x, lane = tid & 31, wid = tid >> 5;
    if (tid == 0) { carry_s = 0; rowptr[0] = 0; }
    __syncthreads();
    for (int base = 0; base < n; base += 1024) {
        int i = base + tid;
        int v = (i < n) ? cnt[i] : 0;
        int x = v;
#pragma unroll
        for (int off = 1; off < 32; off <<= 1) {
            int t = __shfl_up_sync(FULLMASK, x, off);
            if (lane >= off) x += t;
        }
        if (lane == 31) wsum[wid] = x;
        __syncthreads();
        if (wid == 0) {
            int w = wsum[lane];
#pragma unroll
            for (int off = 1; off < 32; off <<= 1) {
                int t = __shfl_up_sync(FULLMASK, w, off);
                if (lane >= off) w += t;
            }
            wsum[lane] = w;
        }
        __syncthreads();
        int incl = x + (wid > 0 ? wsum[wid - 1] : 0) + carry_s;
        if (i < n) { rowptr[i + 1] = incl; cursor[i] = incl - v; }
        __syncthreads();
        if (tid == 1023) carry_s = incl;
        __syncthreads();
    }
}

__global__ void k_scatter(const int* __restrict__ ei, int* cursor,
                          int* __restrict__ csrc, int* __restrict__ ceid, int E) {
    int e = blockIdx.x * blockDim.x + threadIdx.x;
    if (e < E) {
        int dst = ei[E + e];
        int p = atomicAdd(&cursor[dst], 1);
        csrc[p] = ei[e];
        ceid[p] = e;
    }
}

__global__ void k_gather_ea(const float* __restrict__ EA, const int* __restrict__ ceid,
                            float* __restrict__ eacsr, int E) {
    int p = blockIdx.x * blockDim.x + threadIdx.x;
    if (p < E) {
        int e = ceid[p];
        const float4* s = (const float4*)(EA + (long)e * 16);
        float4* d = (float4*)(eacsr + (long)p * 16);
        d[0] = s[0]; d[1] = s[1]; d[2] = s[2]; d[3] = s[3];
    }
}

// ---------------- tf32 tensor-core GEMM (2xTF32 split precision) -------------
// C[M,N] = A[M,K]@B[K,N] + bias. Block 128x64, 256 thr, 8 warps of 32x32.
// D = Ah*Bh + Ah*Bl + Al*Bh (Al*Bl ~ eps^2, dropped) -> fp32-class accuracy.
__global__ __launch_bounds__(256, 3)
void k_gemm_tf32(const float* __restrict__ A, const float* __restrict__ B,
                 const float* __restrict__ bias, float* __restrict__ C,
                 int M, int N, int K)
{
    __shared__ unsigned Ah[16][132], Al[16][132];
    __shared__ unsigned Bh[16][68],  Bl[16][68];

    const int t = threadIdx.x;
    const int lane = t & 31;
    const int warp = t >> 5;
    const int wm = warp & 3;        // 4 warps over M
    const int wn = warp >> 2;       // 2 warps over N
    const int m0 = blockIdx.y * 128;
    const int n0 = blockIdx.x * 64;
    const int g  = lane >> 2;       // groupID 0..7
    const int tg = lane & 3;        // thread-in-group 0..3

    const int ar = t >> 1, ak = (t & 1) * 8;   // A: 2 float4 per thread
    const int bk = t >> 4, bn = (t & 15) * 4;  // B: 1 float4 per thread

    float c[2][4][4];
#pragma unroll
    for (int i = 0; i < 2; i++)
#pragma unroll
        for (int j = 0; j < 4; j++)
#pragma unroll
            for (int q = 0; q < 4; q++) c[i][j][q] = 0.f;

    for (int k0 = 0; k0 < K; k0 += 16) {
        // ---- global -> smem with hi/lo tf32 split ----
        {
            float4 av0 = make_float4(0.f, 0.f, 0.f, 0.f);
            float4 av1 = av0;
            if (m0 + ar < M) {
                const float* ap = A + (long)(m0 + ar) * K + k0 + ak;
                av0 = *(const float4*)ap;
                av1 = *(const float4*)(ap + 4);
            }
            float va[8] = {av0.x, av0.y, av0.z, av0.w, av1.x, av1.y, av1.z, av1.w};
#pragma unroll
            for (int q = 0; q < 8; q++) {
                unsigned hi = f2tf(va[q]);
                float lo = va[q] - __uint_as_float(hi);
                Ah[ak + q][ar] = hi;
                Al[ak + q][ar] = f2tf(lo);
            }
            float4 bv = *(const float4*)(B + (long)(k0 + bk) * N + n0 + bn);
            float vb[4] = {bv.x, bv.y, bv.z, bv.w};
#pragma unroll
            for (int q = 0; q < 4; q++) {
                unsigned hi = f2tf(vb[q]);
                float lo = vb[q] - __uint_as_float(hi);
                Bh[bk][bn + q] = hi;
                Bl[bk][bn + q] = f2tf(lo);
            }
        }
        __syncthreads();

        // ---- mma over two k-frags ----
#pragma unroll
        for (int kf = 0; kf < 2; kf++) {
            int kb = kf * 8;
            unsigned ah[2][4], al[2][4];
#pragma unroll
            for (int i = 0; i < 2; i++) {
                int mrow = wm * 32 + i * 16 + g;
                ah[i][0] = Ah[kb + tg][mrow];
                ah[i][1] = Ah[kb + tg][mrow + 8];
                ah[i][2] = Ah[kb + tg + 4][mrow];
                ah[i][3] = Ah[kb + tg + 4][mrow + 8];
                al[i][0] = Al[kb + tg][mrow];
                al[i][1] = Al[kb + tg][mrow + 8];
                al[i][2] = Al[kb + tg + 4][mrow];
                al[i][3] = Al[kb + tg + 4][mrow + 8];
            }
#pragma unroll
            for (int j = 0; j < 4; j++) {
                int ncol = wn * 32 + j * 8 + g;
                unsigned bh[2], bl[2];
                bh[0] = Bh[kb + tg][ncol];
                bh[1] = Bh[kb + tg + 4][ncol];
                bl[0] = Bl[kb + tg][ncol];
                bl[1] = Bl[kb + tg + 4][ncol];
#pragma unroll
                for (int i = 0; i < 2; i++) {
                    mma_tf32(c[i][j], ah[i], bh);
                    mma_tf32(c[i][j], ah[i], bl);
                    mma_tf32(c[i][j], al[i], bh);
                }
            }
        }
        __syncthreads();
    }

    // ---- epilogue with bias ----
#pragma unroll
    for (int i = 0; i < 2; i++) {
        int row0 = m0 + wm * 32 + i * 16 + g;
        int row1 = row0 + 8;
#pragma unroll
        for (int j = 0; j < 4; j++) {
            int col = n0 + wn * 32 + j * 8 + 2 * tg;
            float b0 = bias[col], b1 = bias[col + 1];
            if (row0 < M) {
                float2 o = make_float2(c[i][j][0] + b0, c[i][j][1] + b1);
                *(float2*)(C + (long)row0 * N + col) = o;
            }
            if (row1 < M) {
                float2 o = make_float2(c[i][j][2] + b0, c[i][j][3] + b1);
                *(float2*)(C + (long)row1 * N + col) = o;
            }
        }
    }
}

// ---------------- GATv2 attention + aggregation (R7 best-known) --------------
template<int HC, int C, bool CONCAT>
__global__ __launch_bounds__(128)
void k_gat(const float* __restrict__ XL, const float* __restrict__ XR,
           const float* __restrict__ EACSR, const float* __restrict__ att,
           const float* __restrict__ bias, const float* __restrict__ We,
           const int* __restrict__ rowptr, const int* __restrict__ csrc,
           float* __restrict__ Hout, int N)
{
    constexpr int WPN = HC / 256;
    constexpr int LPH = C / 8;
    __shared__ float s_red[2][128];

    int widx = threadIdx.x >> 5;
    int lane = threadIdx.x & 31;
    int gw = blockIdx.x * 4 + widx;
    int n = gw / WPN;
    int half = gw - n * WPN;
    int cbase = half * 256 + lane * 8;

    ull w2[16][4];
#pragma unroll
    for (int k = 0; k < 16; k++) {
        const ulonglong2* q = (const ulonglong2*)(We + k * HC + cbase);
        ulonglong2 u0 = q[0], u1 = q[1];
        w2[k][0] = u0.x; w2[k][1] = u0.y; w2[k][2] = u1.x; w2[k][3] = u1.y;
    }
    float att_r[8];
    {
        float4 a = *(const float4*)(att + cbase);
        float4 b = *(const float4*)(att + cbase + 4);
        att_r[0] = a.x; att_r[1] = a.y; att_r[2] = a.z; att_r[3] = a.w;
        att_r[4] = b.x; att_r[5] = b.y; att_r[6] = b.z; att_r[7] = b.w;
    }
    ull xr2[4];
    {
        const ulonglong2* q = (const ulonglong2*)(XR + (long)n * HC + cbase);
        ulonglong2 u0 = q[0], u1 = q[1];
        xr2[0] = u0.x; xr2[1] = u0.y; xr2[2] = u1.x; xr2[3] = u1.y;
    }

    int e0 = rowptr[n], e1 = rowptr[n + 1];
    float m = -3.0e38f, s = 0.f;
    ull acc2[4] = {0ULL, 0ULL, 0ULL, 0ULL};

    float4 cA, cB, cC, cD;
    if (e0 < e1) {
        const float4* q = (const float4*)(EACSR + (long)e0 * 16);
        cA = q[0]; cB = q[1]; cC = q[2]; cD = q[3];
    }

    for (int pb = e0; pb < e1; pb += 32) {
        int myp = pb + lane;
        int msrc = __ldg(&csrc[(myp < e1) ? myp : e1 - 1]);
        int cnt = min(32, e1 - pb);

        ulonglong2 cx0, cx1;
        {
            int s0 = __shfl_sync(FULLMASK, msrc, 0);
            const ulonglong2* xq = (const ulonglong2*)(XL + (long)s0 * HC + cbase);
            cx0 = xq[0]; cx1 = xq[1];
        }
        for (int i = 0; i < cnt; i++) {
            float4 uA = cA, uB = cB, uC = cC, uD = cD;
            ulonglong2 ux0 = cx0, ux1 = cx1;
            if (pb + i + 1 < e1) {
                const float4* q = (const float4*)(EACSR + (long)(pb + i + 1) * 16);
                cA = q[0]; cB = q[1]; cC = q[2]; cD = q[3];
            }
            if (i + 1 < cnt) {
                int sn = __shfl_sync(FULLMASK, msrc, i + 1);
                const ulonglong2* xq = (const ulonglong2*)(XL + (long)sn * HC + cbase);
                cx0 = xq[0]; cx1 = xq[1];
            }
            float ea[16] = {uA.x, uA.y, uA.z, uA.w, uB.x, uB.y, uB.z, uB.w,
                            uC.x, uC.y, uC.z, uC.w, uD.x, uD.y, uD.z, uD.w};
            ull xl2[4] = {ux0.x, ux0.y, ux1.x, ux1.y};

            ull v0 = add2(xl2[0], xr2[0]);
            ull v1 = add2(xl2[1], xr2[1]);
            ull v2 = add2(xl2[2], xr2[2]);
            ull v3 = add2(xl2[3], xr2[3]);
#pragma unroll
            for (int k = 0; k < 16; k++) {
                ull ak = dup2(ea[k]);
                fma2(v0, ak, w2[k][0]);
                fma2(v1, ak, w2[k][1]);
                fma2(v2, ak, w2[k][2]);
                fma2(v3, ak, w2[k][3]);
            }
            float f[8];
            unpack2(v0, f[0], f[1]); unpack2(v1, f[2], f[3]);
            unpack2(v2, f[4], f[5]); unpack2(v3, f[6], f[7]);
            float part = 0.f;
#pragma unroll
            for (int j = 0; j < 8; j++) {
                float vv = f[j];
                part = fmaf(att_r[j], fmaxf(vv, 0.2f * vv), part);
            }
#pragma unroll
            for (int off = 1; off < LPH; off <<= 1)
                part += __shfl_xor_sync(FULLMASK, part, off);

            if (part > m) {
                float sc = __expf(m - part);
                s *= sc;
                ull sc2 = dup2(sc);
#pragma unroll
                for (int j = 0; j < 4; j++) acc2[j] = mul2(acc2[j], sc2);
                m = part;
            }
            float pe = __expf(part - m);
            s += pe;
            ull pe2 = dup2(pe);
            fma2(acc2[0], pe2, xl2[0]);
            fma2(acc2[1], pe2, xl2[1]);
            fma2(acc2[2], pe2, xl2[2]);
            fma2(acc2[3], pe2, xl2[3]);
        }
    }

    float inv = (e1 > e0) ? (1.f / s) : 0.f;
    float r[8];
    unpack2(acc2[0], r[0], r[1]); unpack2(acc2[1], r[2], r[3]);
    unpack2(acc2[2], r[4], r[5]); unpack2(acc2[3], r[6], r[7]);

    if (CONCAT) {
        float4 b0 = *(const float4*)(bias + cbase);
        float4 b1 = *(const float4*)(bias + cbase + 4);
        float4 o0, o1;
        o0.x = fmaf(r[0], inv, b0.x); o0.y = fmaf(r[1], inv, b0.y);
        o0.z = fmaf(r[2], inv, b0.z); o0.w = fmaf(r[3], inv, b0.w);
        o1.x = fmaf(r[4], inv, b1.x); o1.y = fmaf(r[5], inv, b1.y);
        o1.z = fmaf(r[6], inv, b1.z); o1.w = fmaf(r[7], inv, b1.w);
        float* q = Hout + (long)n * HC + cbase;
        *(float4*)q = o0;
        *(float4*)(q + 4) = o1;
    } else {
#pragma unroll
        for (int j = 0; j < 8; j++) {
            r[j] *= inv;
            r[j] += __shfl_xor_sync(FULLMASK, r[j], 16);
        }
        int nib = widx >> 1;
        int c = (lane & 15) * 8;
        if (half == 0 && lane < 16) {
#pragma unroll
            for (int j = 0; j < 8; j++) s_red[nib][c + j] = r[j];
        }
        __syncthreads();
        if (half == 1 && lane < 16) {
            float* q = Hout + (long)n * C + c;
#pragma unroll
            for (int j = 0; j < 8; j++)
                q[j] = bias[c + j] + 0.25f * (r[j] + s_red[nib][c + j]);
        }
    }
}

// ---------------- pooling ----------------------------------------------------
__global__ void k_pool_init(float* out, int* gcnt) {
    int i = blockIdx.x * blockDim.x + threadIdx.x;
    if (i < NG * 256) out[i] = ((i & 255) < 128) ? -FLT_MAX : 0.f;
    if (i < NG) gcnt[i] = 0;
}

__global__ void k_pool_acc(const float* __restrict__ H, const int* __restrict__ batch,
                           float* out, int* gcnt) {
    int i = blockIdx.x * blockDim.x + threadIdx.x;
    if (i >= NN * 128) return;
    int nd = i >> 7, c = i & 127;
    int g = batch[nd];
    float v = H[i];
    float* mx = out + g * 256 + c;
    if (v >= 0.f) atomicMax((int*)mx, __float_as_int(v));
    else atomicMin((unsigned int*)mx, __float_as_uint(v));
    atomicAdd(out + g * 256 + 128 + c, v);
    if (c == 0) atomicAdd(&gcnt[g], 1);
}

__global__ void k_pool_fin(float* out, const int* __restrict__ gcnt) {
    int i = blockIdx.x * blockDim.x + threadIdx.x;
    if (i < NG * 128) {
        int g = i >> 7, c = i & 127;
        float cnt = (float)(gcnt[g] > 0 ? gcnt[g] : 1);
        out[g * 256 + 128 + c] /= cnt;
    }
}

// ---------------- launch -----------------------------------------------------
extern "C" void kernel_launch(void* const* d_in, const int* in_sizes, int n_in,
                              void* d_out, int out_size)
{
    const float* x     = (const float*)d_in[0];
    const float* ea    = (const float*)d_in[1];
    const int*   ei    = (const int*)d_in[2];
    const int*   batch = (const int*)d_in[3];
    const float* Wl[3] = {(const float*)d_in[4],  (const float*)d_in[11], (const float*)d_in[18]};
    const float* bl[3] = {(const float*)d_in[5],  (const float*)d_in[12], (const float*)d_in[19]};
    const float* Wr[3] = {(const float*)d_in[6],  (const float*)d_in[13], (const float*)d_in[20]};
    const float* br[3] = {(const float*)d_in[7],  (const float*)d_in[14], (const float*)d_in[21]};
    const float* We[3] = {(const float*)d_in[8],  (const float*)d_in[15], (const float*)d_in[22]};
    const float* At[3] = {(const float*)d_in[9],  (const float*)d_in[16], (const float*)d_in[23]};
    const float* Bi[3] = {(const float*)d_in[10], (const float*)d_in[17], (const float*)d_in[24]};
    float* out = (float*)d_out;

    float *XL, *XR, *HA, *HB, *eacsr;
    int *cnt, *rowptr, *cursor, *csrc, *ceid, *gcnt;
    cudaGetSymbolAddress((void**)&XL, g_XL);
    cudaGetSymbolAddress((void**)&XR, g_XR);
    cudaGetSymbolAddress((void**)&HA, g_HA);
    cudaGetSymbolAddress((void**)&HB, g_HB);
    cudaGetSymbolAddress((void**)&cnt, g_cnt);
    cudaGetSymbolAddress((void**)&rowptr, g_rowptr);
    cudaGetSymbolAddress((void**)&cursor, g_cursor);
    cudaGetSymbolAddress((void**)&csrc, g_csrc);
    cudaGetSymbolAddress((void**)&ceid, g_ceid);
    cudaGetSymbolAddress((void**)&eacsr, g_eacsr);
    cudaGetSymbolAddress((void**)&gcnt, g_gcnt);

    const int MT = (NN + 127) / 128;  // 157

    // ---- CSR histogram + scan (launches 1-3) ----
    k_zero_cnt<<<(NN + 255) / 256, 256>>>(cnt, NN);
    k_hist<<<(NE + 255) / 256, 256>>>(ei, cnt, NE);
    k_scan<<<1, 1024>>>(cnt, rowptr, cursor, NN);

    // ---- launch 4 = ncu capture slot: first tf32 GEMM ----
    k_gemm_tf32<<<dim3(4, MT), 256>>>(x, Wl[0], bl[0], XL, NN, 256, 128);
    k_gemm_tf32<<<dim3(4, MT), 256>>>(x, Wr[0], br[0], XR, NN, 256, 128);

    // ---- finish CSR ----
    k_scatter<<<(NE + 255) / 256, 256>>>(ei, cursor, csrc, ceid, NE);
    k_gather_ea<<<(NE + 255) / 256, 256>>>(ea, ceid, eacsr, NE);

    // ---- layer 0 attention ----
    k_gat<256, 64, true><<<NN / 4, 128>>>(XL, XR, eacsr, At[0], Bi[0], We[0],
                                          rowptr, csrc, HA, NN);

    // ---- layer 1 ----
    k_gemm_tf32<<<dim3(4, MT), 256>>>(HA, Wl[1], bl[1], XL, NN, 256, 256);
    k_gemm_tf32<<<dim3(4, MT), 256>>>(HA, Wr[1], br[1], XR, NN, 256, 256);
    k_gat<256, 64, true><<<NN / 4, 128>>>(XL, XR, eacsr, At[1], Bi[1], We[1],
                                          rowptr, csrc, HB, NN);

    // ---- layer 2 (mean over heads) ----
    k_gemm_tf32<<<dim3(8, MT), 256>>>(HB, Wl[2], bl[2], XL, NN, 512, 256);
    k_gemm_tf32<<<dim3(8, MT), 256>>>(HB, Wr[2], br[2], XR, NN, 512, 256);
    k_gat<512, 128, false><<<NN * 2 / 4, 128>>>(XL, XR, eacsr, At[2], Bi[2], We[2],
                                                rowptr, csrc, HA, NN);

    // ---- pooling ----
    k_pool_init<<<64, 256>>>(out, gcnt);
    k_pool_acc<<<(NN * 128 + 255) / 256, 256>>>(HA, batch, out, gcnt);
    k_pool_fin<<<32, 256>>>(out, gcnt);
}

// round 13
// speedup vs baseline: 1.0453x; 1.0453x over previous
#include <cuda_runtime.h>
#include <float.h>
#include <math.h>

#define FULLMASK 0xffffffffu

typedef unsigned long long ull;

static const int NN = 20000;   // nodes
static const int NE = 640000;  // edges
static const int NG = 64;      // graphs

// ---------------- packed f32x2 helpers (Blackwell FFMA2 path) ----------------
__device__ __forceinline__ ull pack2(float x, float y) {
    ull r; asm("mov.b64 %0,{%1,%2};" : "=l"(r) : "f"(x), "f"(y)); return r;
}
__device__ __forceinline__ ull dup2(float x) { return pack2(x, x); }
__device__ __forceinline__ void unpack2(ull v, float& x, float& y) {
    asm("mov.b64 {%0,%1},%2;" : "=f"(x), "=f"(y) : "l"(v));
}
__device__ __forceinline__ void fma2(ull& d, ull a, ull b) {
    asm("fma.rn.f32x2 %0,%1,%2,%0;" : "+l"(d) : "l"(a), "l"(b));
}
__device__ __forceinline__ ull add2(ull a, ull b) {
    ull r; asm("add.rn.f32x2 %0,%1,%2;" : "=l"(r) : "l"(a), "l"(b)); return r;
}
__device__ __forceinline__ ull mul2(ull a, ull b) {
    ull r; asm("mul.rn.f32x2 %0,%1,%2;" : "=l"(r) : "l"(a), "l"(b)); return r;
}

// ---------------- scratch ----------------------------------------------------
__device__ float g_XL[20000 * 512];
__device__ float g_XR[20000 * 512];
__device__ float g_HA[20000 * 256];
__device__ float g_HB[20000 * 256];
__device__ int   g_cnt[20000];
__device__ int   g_rowptr[20001];
__device__ int   g_cursor[20000];
__device__ int   g_csrc[640000];
__device__ int   g_ceid[640000];
__device__ __align__(16) float g_eacsr[640000 * 16];
__device__ int   g_gcnt[64];

// ---------------- CSR build --------------------------------------------------
__global__ void k_zero_cnt(int* cnt, int n) {
    int i = blockIdx.x * blockDim.x + threadIdx.x;
    if (i < n) cnt[i] = 0;
}

__global__ void k_hist(const int* __restrict__ ei, int* cnt, int E) {
    int e = blockIdx.x * blockDim.x + threadIdx.x;
    if (e < E) atomicAdd(&cnt[ei[E + e]], 1);
}

__global__ void k_scan(const int* __restrict__ cnt, int* rowptr, int* cursor, int n) {
    __shared__ int wsum[32];
    __shared__ int carry_s;
    int tid = threadIdx.x, lane = tid & 31, wid = tid >> 5;
    if (tid == 0) { carry_s = 0; rowptr[0] = 0; }
    __syncthreads();
    for (int base = 0; base < n; base += 1024) {
        int i = base + tid;
        int v = (i < n) ? cnt[i] : 0;
        int x = v;
#pragma unroll
        for (int off = 1; off < 32; off <<= 1) {
            int t = __shfl_up_sync(FULLMASK, x, off);
            if (lane >= off) x += t;
        }
        if (lane == 31) wsum[wid] = x;
        __syncthreads();
        if (wid == 0) {
            int w = wsum[lane];
#pragma unroll
            for (int off = 1; off < 32; off <<= 1) {
                int t = __shfl_up_sync(FULLMASK, w, off);
                if (lane >= off) w += t;
            }
            wsum[lane] = w;
        }
        __syncthreads();
        int incl = x + (wid > 0 ? wsum[wid - 1] : 0) + carry_s;
        if (i < n) { rowptr[i + 1] = incl; cursor[i] = incl - v; }
        __syncthreads();
        if (tid == 1023) carry_s = incl;
        __syncthreads();
    }
}

__global__ void k_scatter(const int* __restrict__ ei, int* cursor,
                          int* __restrict__ csrc, int* __restrict__ ceid, int E) {
    int e = blockIdx.x * blockDim.x + threadIdx.x;
    if (e < E) {
        int dst = ei[E + e];
        int p = atomicAdd(&cursor[dst], 1);
        csrc[p] = ei[e];
        ceid[p] = e;
    }
}

__global__ void k_gather_ea(const float* __restrict__ EA, const int* __restrict__ ceid,
                            float* __restrict__ eacsr, int E) {
    int p = blockIdx.x * blockDim.x + threadIdx.x;
    if (p < E) {
        int e = ceid[p];
        const float4* s = (const float4*)(EA + (long)e * 16);
        float4* d = (float4*)(eacsr + (long)p * 16);
        d[0] = s[0]; d[1] = s[1]; d[2] = s[2]; d[3] = s[3];
    }
}

// ---------------- fp32 GEMM (FFMA2), double-buffered smem --------------------
// BM=128, BN=64, BK=8, 256 threads, 8x4 micro-tile, 2 smem stages ->
// ONE __syncthreads per k-tile; gmem latency hidden behind compute.
__global__ __launch_bounds__(256, 3)
void k_gemm_bias(const float* __restrict__ A, const float* __restrict__ B,
                 const float* __restrict__ bias, float* __restrict__ C,
                 int M, int N, int K)
{
    __shared__ __align__(16) float As[2][8][132];
    __shared__ __align__(16) float Bs[2][8][64];
    const int t = threadIdx.x;
    const int m0 = blockIdx.y * 128;
    const int n0 = blockIdx.x * 64;
    const int tx = t & 15, ty = t >> 4;
    const int ar = t >> 1, ak = (t & 1) * 4;
    const int bk = t >> 4, bn = (t & 15) * 4;

    ull c2[8][2];
#pragma unroll
    for (int i = 0; i < 8; i++) { c2[i][0] = 0ULL; c2[i][1] = 0ULL; }

    // stage 0 fill
    {
        float4 av = make_float4(0.f, 0.f, 0.f, 0.f);
        if (m0 + ar < M) av = *(const float4*)(A + (long)(m0 + ar) * K + ak);
        As[0][ak + 0][ar] = av.x;
        As[0][ak + 1][ar] = av.y;
        As[0][ak + 2][ar] = av.z;
        As[0][ak + 3][ar] = av.w;
        if (t < 128) {
            float4 bv = *(const float4*)(B + (long)bk * N + n0 + bn);
            *(float4*)&Bs[0][bk][bn] = bv;
        }
    }
    __syncthreads();

    int st = 0;
    for (int k0 = 0; k0 < K; k0 += 8) {
        bool more = (k0 + 8 < K);
        float4 av = make_float4(0.f, 0.f, 0.f, 0.f);
        float4 bv = make_float4(0.f, 0.f, 0.f, 0.f);
        if (more) {
            if (m0 + ar < M) av = *(const float4*)(A + (long)(m0 + ar) * K + k0 + 8 + ak);
            if (t < 128) bv = *(const float4*)(B + (long)(k0 + 8 + bk) * N + n0 + bn);
        }

#pragma unroll
        for (int kk = 0; kk < 8; kk++) {
            float4 a0 = *(const float4*)&As[st][kk][ty * 8];
            float4 a1 = *(const float4*)&As[st][kk][ty * 8 + 4];
            ulonglong2 bb = *(const ulonglong2*)&Bs[st][kk][tx * 4];
            ull ad[8];
            ad[0] = dup2(a0.x); ad[1] = dup2(a0.y); ad[2] = dup2(a0.z); ad[3] = dup2(a0.w);
            ad[4] = dup2(a1.x); ad[5] = dup2(a1.y); ad[6] = dup2(a1.z); ad[7] = dup2(a1.w);
#pragma unroll
            for (int i = 0; i < 8; i++) {
                fma2(c2[i][0], ad[i], bb.x);
                fma2(c2[i][1], ad[i], bb.y);
            }
        }
        if (more) {
            int nxt = st ^ 1;
            As[nxt][ak + 0][ar] = av.x;
            As[nxt][ak + 1][ar] = av.y;
            As[nxt][ak + 2][ar] = av.z;
            As[nxt][ak + 3][ar] = av.w;
            if (t < 128) *(float4*)&Bs[nxt][bk][bn] = bv;
            __syncthreads();
            st = nxt;
        }
    }

    float4 bb = *(const float4*)(bias + n0 + tx * 4);
#pragma unroll
    for (int i = 0; i < 8; i++) {
        int row = m0 + ty * 8 + i;
        if (row < M) {
            float4 o;
            unpack2(c2[i][0], o.x, o.y);
            unpack2(c2[i][1], o.z, o.w);
            o.x += bb.x; o.y += bb.y; o.z += bb.z; o.w += bb.w;
            *(float4*)(C + (long)row * N + n0 + tx * 4) = o;
        }
    }
}

// ---------------- GATv2 attention + aggregation (R7 best-known) --------------
template<int HC, int C, bool CONCAT>
__global__ __launch_bounds__(128)
void k_gat(const float* __restrict__ XL, const float* __restrict__ XR,
           const float* __restrict__ EACSR, const float* __restrict__ att,
           const float* __restrict__ bias, const float* __restrict__ We,
           const int* __restrict__ rowptr, const int* __restrict__ csrc,
           float* __restrict__ Hout, int N)
{
    constexpr int WPN = HC / 256;
    constexpr int LPH = C / 8;
    __shared__ float s_red[2][128];

    int widx = threadIdx.x >> 5;
    int lane = threadIdx.x & 31;
    int gw = blockIdx.x * 4 + widx;
    int n = gw / WPN;
    int half = gw - n * WPN;
    int cbase = half * 256 + lane * 8;

    ull w2[16][4];
#pragma unroll
    for (int k = 0; k < 16; k++) {
        const ulonglong2* q = (const ulonglong2*)(We + k * HC + cbase);
        ulonglong2 u0 = q[0], u1 = q[1];
        w2[k][0] = u0.x; w2[k][1] = u0.y; w2[k][2] = u1.x; w2[k][3] = u1.y;
    }
    float att_r[8];
    {
        float4 a = *(const float4*)(att + cbase);
        float4 b = *(const float4*)(att + cbase + 4);
        att_r[0] = a.x; att_r[1] = a.y; att_r[2] = a.z; att_r[3] = a.w;
        att_r[4] = b.x; att_r[5] = b.y; att_r[6] = b.z; att_r[7] = b.w;
    }
    ull xr2[4];
    {
        const ulonglong2* q = (const ulonglong2*)(XR + (long)n * HC + cbase);
        ulonglong2 u0 = q[0], u1 = q[1];
        xr2[0] = u0.x; xr2[1] = u0.y; xr2[2] = u1.x; xr2[3] = u1.y;
    }

    int e0 = rowptr[n], e1 = rowptr[n + 1];
    float m = -3.0e38f, s = 0.f;
    ull acc2[4] = {0ULL, 0ULL, 0ULL, 0ULL};

    float4 cA, cB, cC, cD;
    if (e0 < e1) {
        const float4* q = (const float4*)(EACSR + (long)e0 * 16);
        cA = q[0]; cB = q[1]; cC = q[2]; cD = q[3];
    }

    for (int pb = e0; pb < e1; pb += 32) {
        int myp = pb + lane;
        int msrc = __ldg(&csrc[(myp < e1) ? myp : e1 - 1]);
        int cnt = min(32, e1 - pb);

        ulonglong2 cx0, cx1;
        {
            int s0 = __shfl_sync(FULLMASK, msrc, 0);
            const ulonglong2* xq = (const ulonglong2*)(XL + (long)s0 * HC + cbase);
            cx0 = xq[0]; cx1 = xq[1];
        }
        for (int i = 0; i < cnt; i++) {
            float4 uA = cA, uB = cB, uC = cC, uD = cD;
            ulonglong2 ux0 = cx0, ux1 = cx1;
            if (pb + i + 1 < e1) {
                const float4* q = (const float4*)(EACSR + (long)(pb + i + 1) * 16);
                cA = q[0]; cB = q[1]; cC = q[2]; cD = q[3];
            }
            if (i + 1 < cnt) {
                int sn = __shfl_sync(FULLMASK, msrc, i + 1);
                const ulonglong2* xq = (const ulonglong2*)(XL + (long)sn * HC + cbase);
                cx0 = xq[0]; cx1 = xq[1];
            }
            float ea[16] = {uA.x, uA.y, uA.z, uA.w, uB.x, uB.y, uB.z, uB.w,
                            uC.x, uC.y, uC.z, uC.w, uD.x, uD.y, uD.z, uD.w};
            ull xl2[4] = {ux0.x, ux0.y, ux1.x, ux1.y};

            ull v0 = add2(xl2[0], xr2[0]);
            ull v1 = add2(xl2[1], xr2[1]);
            ull v2 = add2(xl2[2], xr2[2]);
            ull v3 = add2(xl2[3], xr2[3]);
#pragma unroll
            for (int k = 0; k < 16; k++) {
                ull ak = dup2(ea[k]);
                fma2(v0, ak, w2[k][0]);
                fma2(v1, ak, w2[k][1]);
                fma2(v2, ak, w2[k][2]);
                fma2(v3, ak, w2[k][3]);
            }
            float f[8];
            unpack2(v0, f[0], f[1]); unpack2(v1, f[2], f[3]);
            unpack2(v2, f[4], f[5]); unpack2(v3, f[6], f[7]);
            float part = 0.f;
#pragma unroll
            for (int j = 0; j < 8; j++) {
                float vv = f[j];
                part = fmaf(att_r[j], fmaxf(vv, 0.2f * vv), part);
            }
#pragma unroll
            for (int off = 1; off < LPH; off <<= 1)
                part += __shfl_xor_sync(FULLMASK, part, off);

            if (part > m) {
                float sc = __expf(m - part);
                s *= sc;
                ull sc2 = dup2(sc);
#pragma unroll
                for (int j = 0; j < 4; j++) acc2[j] = mul2(acc2[j], sc2);
                m = part;
            }
            float pe = __expf(part - m);
            s += pe;
            ull pe2 = dup2(pe);
            fma2(acc2[0], pe2, xl2[0]);
            fma2(acc2[1], pe2, xl2[1]);
            fma2(acc2[2], pe2, xl2[2]);
            fma2(acc2[3], pe2, xl2[3]);
        }
    }

    float inv = (e1 > e0) ? (1.f / s) : 0.f;
    float r[8];
    unpack2(acc2[0], r[0], r[1]); unpack2(acc2[1], r[2], r[3]);
    unpack2(acc2[2], r[4], r[5]); unpack2(acc2[3], r[6], r[7]);

    if (CONCAT) {
        float4 b0 = *(const float4*)(bias + cbase);
        float4 b1 = *(const float4*)(bias + cbase + 4);
        float4 o0, o1;
        o0.x = fmaf(r[0], inv, b0.x); o0.y = fmaf(r[1], inv, b0.y);
        o0.z = fmaf(r[2], inv, b0.z); o0.w = fmaf(r[3], inv, b0.w);
        o1.x = fmaf(r[4], inv, b1.x); o1.y = fmaf(r[5], inv, b1.y);
        o1.z = fmaf(r[6], inv, b1.z); o1.w = fmaf(r[7], inv, b1.w);
        float* q = Hout + (long)n * HC + cbase;
        *(float4*)q = o0;
        *(float4*)(q + 4) = o1;
    } else {
#pragma unroll
        for (int j = 0; j < 8; j++) {
            r[j] *= inv;
            r[j] += __shfl_xor_sync(FULLMASK, r[j], 16);
        }
        int nib = widx >> 1;
        int c = (lane & 15) * 8;
        if (half == 0 && lane < 16) {
#pragma unroll
            for (int j = 0; j < 8; j++) s_red[nib][c + j] = r[j];
        }
        __syncthreads();
        if (half == 1 && lane < 16) {
            float* q = Hout + (long)n * C + c;
#pragma unroll
            for (int j = 0; j < 8; j++)
                q[j] = bias[c + j] + 0.25f * (r[j] + s_red[nib][c + j]);
        }
    }
}

// ---------------- pooling ----------------------------------------------------
__global__ void k_pool_init(float* out, int* gcnt) {
    int i = blockIdx.x * blockDim.x + threadIdx.x;
    if (i < NG * 256) out[i] = ((i & 255) < 128) ? -FLT_MAX : 0.f;
    if (i < NG) gcnt[i] = 0;
}

__global__ void k_pool_acc(const float* __restrict__ H, const int* __restrict__ batch,
                           float* out, int* gcnt) {
    int i = blockIdx.x * blockDim.x + threadIdx.x;
    if (i >= NN * 128) return;
    int nd = i >> 7, c = i & 127;
    int g = batch[nd];
    float v = H[i];
    float* mx = out + g * 256 + c;
    if (v >= 0.f) atomicMax((int*)mx, __float_as_int(v));
    else atomicMin((unsigned int*)mx, __float_as_uint(v));
    atomicAdd(out + g * 256 + 128 + c, v);
    if (c == 0) atomicAdd(&gcnt[g], 1);
}

__global__ void k_pool_fin(float* out, const int* __restrict__ gcnt) {
    int i = blockIdx.x * blockDim.x + threadIdx.x;
    if (i < NG * 128) {
        int g = i >> 7, c = i & 127;
        float cnt = (float)(gcnt[g] > 0 ? gcnt[g] : 1);
        out[g * 256 + 128 + c] /= cnt;
    }
}

// ---------------- launch -----------------------------------------------------
extern "C" void kernel_launch(void* const* d_in, const int* in_sizes, int n_in,
                              void* d_out, int out_size)
{
    const float* x     = (const float*)d_in[0];
    const float* ea    = (const float*)d_in[1];
    const int*   ei    = (const int*)d_in[2];
    const int*   batch = (const int*)d_in[3];
    const float* Wl[3] = {(const float*)d_in[4],  (const float*)d_in[11], (const float*)d_in[18]};
    const float* bl[3] = {(const float*)d_in[5],  (const float*)d_in[12], (const float*)d_in[19]};
    const float* Wr[3] = {(const float*)d_in[6],  (const float*)d_in[13], (const float*)d_in[20]};
    const float* br[3] = {(const float*)d_in[7],  (const float*)d_in[14], (const float*)d_in[21]};
    const float* We[3] = {(const float*)d_in[8],  (const float*)d_in[15], (const float*)d_in[22]};
    const float* At[3] = {(const float*)d_in[9],  (const float*)d_in[16], (const float*)d_in[23]};
    const float* Bi[3] = {(const float*)d_in[10], (const float*)d_in[17], (const float*)d_in[24]};
    float* out = (float*)d_out;

    float *XL, *XR, *HA, *HB, *eacsr;
    int *cnt, *rowptr, *cursor, *csrc, *ceid, *gcnt;
    cudaGetSymbolAddress((void**)&XL, g_XL);
    cudaGetSymbolAddress((void**)&XR, g_XR);
    cudaGetSymbolAddress((void**)&HA, g_HA);
    cudaGetSymbolAddress((void**)&HB, g_HB);
    cudaGetSymbolAddress((void**)&cnt, g_cnt);
    cudaGetSymbolAddress((void**)&rowptr, g_rowptr);
    cudaGetSymbolAddress((void**)&cursor, g_cursor);
    cudaGetSymbolAddress((void**)&csrc, g_csrc);
    cudaGetSymbolAddress((void**)&ceid, g_ceid);
    cudaGetSymbolAddress((void**)&eacsr, g_eacsr);
    cudaGetSymbolAddress((void**)&gcnt, g_gcnt);

    const int MT = (NN + 127) / 128;  // 157

    // ---- CSR histogram + scan (launches 1-3) ----
    k_zero_cnt<<<(NN + 255) / 256, 256>>>(cnt, NN);
    k_hist<<<(NE + 255) / 256, 256>>>(ei, cnt, NE);
    k_scan<<<1, 1024>>>(cnt, rowptr, cursor, NN);

    // ---- launch 4 = ncu capture slot: first GEMM (double-buffered) ----
    k_gemm_bias<<<dim3(4, MT), 256>>>(x, Wl[0], bl[0], XL, NN, 256, 128);
    k_gemm_bias<<<dim3(4, MT), 256>>>(x, Wr[0], br[0], XR, NN, 256, 128);

    // ---- finish CSR ----
    k_scatter<<<(NE + 255) / 256, 256>>>(ei, cursor, csrc, ceid, NE);
    k_gather_ea<<<(NE + 255) / 256, 256>>>(ea, ceid, eacsr, NE);

    // ---- layer 0 attention ----
    k_gat<256, 64, true><<<NN / 4, 128>>>(XL, XR, eacsr, At[0], Bi[0], We[0],
                                          rowptr, csrc, HA, NN);

    // ---- layer 1 ----
    k_gemm_bias<<<dim3(4, MT), 256>>>(HA, Wl[1], bl[1], XL, NN, 256, 256);
    k_gemm_bias<<<dim3(4, MT), 256>>>(HA, Wr[1], br[1], XR, NN, 256, 256);
    k_gat<256, 64, true><<<NN / 4, 128>>>(XL, XR, eacsr, At[1], Bi[1], We[1],
                                          rowptr, csrc, HB, NN);

    // ---- layer 2 (mean over heads) ----
    k_gemm_bias<<<dim3(8, MT), 256>>>(HB, Wl[2], bl[2], XL, NN, 512, 256);
    k_gemm_bias<<<dim3(8, MT), 256>>>(HB, Wr[2], br[2], XR, NN, 512, 256);
    k_gat<512, 128, false><<<NN * 2 / 4, 128>>>(XL, XR, eacsr, At[2], Bi[2], We[2],
                                                rowptr, csrc, HA, NN);

    // ---- pooling ----
    k_pool_init<<<64, 256>>>(out, gcnt);
    k_pool_acc<<<(NN * 128 + 255) / 256, 256>>>(HA, batch, out, gcnt);
    k_pool_fin<<<32, 256>>>(out, gcnt);
}

// round 15
// speedup vs baseline: 1.1010x; 1.0532x over previous
#include <cuda_runtime.h>
#include <float.h>
#include <math.h>

#define FULLMASK 0xffffffffu

typedef unsigned long long ull;

static const int NN = 20000;   // nodes
static const int NE = 640000;  // edges
static const int NG = 64;      // graphs

// ---------------- packed f32x2 helpers (Blackwell FFMA2 path) ----------------
__device__ __forceinline__ ull pack2(float x, float y) {
    ull r; asm("mov.b64 %0,{%1,%2};" : "=l"(r) : "f"(x), "f"(y)); return r;
}
__device__ __forceinline__ ull dup2(float x) { return pack2(x, x); }
__device__ __forceinline__ void unpack2(ull v, float& x, float& y) {
    asm("mov.b64 {%0,%1},%2;" : "=f"(x), "=f"(y) : "l"(v));
}
__device__ __forceinline__ void fma2(ull& d, ull a, ull b) {
    asm("fma.rn.f32x2 %0,%1,%2,%0;" : "+l"(d) : "l"(a), "l"(b));
}
__device__ __forceinline__ ull add2(ull a, ull b) {
    ull r; asm("add.rn.f32x2 %0,%1,%2;" : "=l"(r) : "l"(a), "l"(b)); return r;
}
__device__ __forceinline__ ull mul2(ull a, ull b) {
    ull r; asm("mul.rn.f32x2 %0,%1,%2;" : "=l"(r) : "l"(a), "l"(b)); return r;
}

// ---------------- scratch ----------------------------------------------------
__device__ float g_XL[20000 * 512];
__device__ float g_XR[20000 * 512];
__device__ float g_HA[20000 * 256];
__device__ float g_HB[20000 * 256];
__device__ int   g_cnt[20000];
__device__ int   g_rowptr[20001];
__device__ int   g_cursor[20000];
__device__ int   g_csrc[640000];
__device__ int   g_ceid[640000];
__device__ __align__(16) float g_eacsr[640000 * 16];
__device__ int   g_gcnt[64];

// ---------------- CSR build --------------------------------------------------
__global__ void k_zero_cnt(int* cnt, int n) {
    int i = blockIdx.x * blockDim.x + threadIdx.x;
    if (i < n) cnt[i] = 0;
}

__global__ void k_hist(const int* __restrict__ ei, int* cnt, int E) {
    int e = blockIdx.x * blockDim.x + threadIdx.x;
    if (e < E) atomicAdd(&cnt[ei[E + e]], 1);
}

__global__ void k_scan(const int* __restrict__ cnt, int* rowptr, int* cursor, int n) {
    __shared__ int wsum[32];
    __shared__ int carry_s;
    int tid = threadIdx.x, lane = tid & 31, wid = tid >> 5;
    if (tid == 0) { carry_s = 0; rowptr[0] = 0; }
    __syncthreads();
    for (int base = 0; base < n; base += 1024) {
        int i = base + tid;
        int v = (i < n) ? cnt[i] : 0;
        int x = v;
#pragma unroll
        for (int off = 1; off < 32; off <<= 1) {
            int t = __shfl_up_sync(FULLMASK, x, off);
            if (lane >= off) x += t;
        }
        if (lane == 31) wsum[wid] = x;
        __syncthreads();
        if (wid == 0) {
            int w = wsum[lane];
#pragma unroll
            for (int off = 1; off < 32; off <<= 1) {
                int t = __shfl_up_sync(FULLMASK, w, off);
                if (lane >= off) w += t;
            }
            wsum[lane] = w;
        }
        __syncthreads();
        int incl = x + (wid > 0 ? wsum[wid - 1] : 0) + carry_s;
        if (i < n) { rowptr[i + 1] = incl; cursor[i] = incl - v; }
        __syncthreads();
        if (tid == 1023) carry_s = incl;
        __syncthreads();
    }
}

__global__ void k_scatter(const int* __restrict__ ei, int* cursor,
                          int* __restrict__ csrc, int* __restrict__ ceid, int E) {
    int e = blockIdx.x * blockDim.x + threadIdx.x;
    if (e < E) {
        int dst = ei[E + e];
        int p = atomicAdd(&cursor[dst], 1);
        csrc[p] = ei[e];
        ceid[p] = e;
    }
}

__global__ void k_gather_ea(const float* __restrict__ EA, const int* __restrict__ ceid,
                            float* __restrict__ eacsr, int E) {
    int p = blockIdx.x * blockDim.x + threadIdx.x;
    if (p < E) {
        int e = ceid[p];
        const float4* s = (const float4*)(EA + (long)e * 16);
        float4* d = (float4*)(eacsr + (long)p * 16);
        d[0] = s[0]; d[1] = s[1]; d[2] = s[2]; d[3] = s[3];
    }
}

// ---------------- fp32 GEMM (FFMA2): C[M,N] = A[M,K]@B[K,N] + bias -----------
// R7 single-stage version (measured best: 44.9us L0, fma=42%).
__global__ __launch_bounds__(256, 3)
void k_gemm_bias(const float* __restrict__ A, const float* __restrict__ B,
                 const float* __restrict__ bias, float* __restrict__ C,
                 int M, int N, int K)
{
    __shared__ __align__(16) float As[8][132];
    __shared__ __align__(16) float Bs[8][64];
    const int t = threadIdx.x;
    const int m0 = blockIdx.y * 128;
    const int n0 = blockIdx.x * 64;
    const int tx = t & 15, ty = t >> 4;
    const int ar = t >> 1, ak = (t & 1) * 4;
    const int bk = t >> 4, bn = (t & 15) * 4;

    ull c2[8][2];
#pragma unroll
    for (int i = 0; i < 8; i++) { c2[i][0] = 0ULL; c2[i][1] = 0ULL; }

    float4 av = make_float4(0.f, 0.f, 0.f, 0.f);
    if (m0 + ar < M) av = *(const float4*)(A + (long)(m0 + ar) * K + ak);
    float4 bv = make_float4(0.f, 0.f, 0.f, 0.f);
    if (t < 128) bv = *(const float4*)(B + (long)bk * N + n0 + bn);

    int k0 = 0;
    for (;;) {
        As[ak + 0][ar] = av.x;
        As[ak + 1][ar] = av.y;
        As[ak + 2][ar] = av.z;
        As[ak + 3][ar] = av.w;
        if (t < 128) *(float4*)&Bs[bk][bn] = bv;
        __syncthreads();

        k0 += 8;
        bool more = (k0 < K);
        if (more) {
            av = make_float4(0.f, 0.f, 0.f, 0.f);
            if (m0 + ar < M) av = *(const float4*)(A + (long)(m0 + ar) * K + k0 + ak);
            if (t < 128) bv = *(const float4*)(B + (long)(k0 + bk) * N + n0 + bn);
        }

#pragma unroll
        for (int kk = 0; kk < 8; kk++) {
            float4 a0 = *(const float4*)&As[kk][ty * 8];
            float4 a1 = *(const float4*)&As[kk][ty * 8 + 4];
            ulonglong2 bb = *(const ulonglong2*)&Bs[kk][tx * 4];
            ull ad[8];
            ad[0] = dup2(a0.x); ad[1] = dup2(a0.y); ad[2] = dup2(a0.z); ad[3] = dup2(a0.w);
            ad[4] = dup2(a1.x); ad[5] = dup2(a1.y); ad[6] = dup2(a1.z); ad[7] = dup2(a1.w);
#pragma unroll
            for (int i = 0; i < 8; i++) {
                fma2(c2[i][0], ad[i], bb.x);
                fma2(c2[i][1], ad[i], bb.y);
            }
        }
        if (!more) break;
        __syncthreads();
    }

    float4 bb = *(const float4*)(bias + n0 + tx * 4);
#pragma unroll
    for (int i = 0; i < 8; i++) {
        int row = m0 + ty * 8 + i;
        if (row < M) {
            float4 o;
            unpack2(c2[i][0], o.x, o.y);
            unpack2(c2[i][1], o.z, o.w);
            o.x += bb.x; o.y += bb.y; o.z += bb.z; o.w += bb.w;
            *(float4*)(C + (long)row * N + n0 + tx * 4) = o;
        }
    }
}

// ---------------- GATv2 attention: warp-granular blocks ----------------------
// 8 ch/lane; warp covers 256 ch; WPN = HC/256 warps per node.
// Launch: CONCAT layers <<<N, 32>>> (one warp = one block = one node, so nodes
// retire independently — no intra-block max-degree gating); layer 2 <<<N, 64>>>
// (the node's 2 cooperating warps share a block for the smem head-mean).
template<int HC, int C, bool CONCAT>
__global__ __launch_bounds__(128)
void k_gat(const float* __restrict__ XL, const float* __restrict__ XR,
           const float* __restrict__ EACSR, const float* __restrict__ att,
           const float* __restrict__ bias, const float* __restrict__ We,
           const int* __restrict__ rowptr, const int* __restrict__ csrc,
           float* __restrict__ Hout, int N)
{
    constexpr int WPN = HC / 256;
    constexpr int LPH = C / 8;
    __shared__ float s_red[128];    // layer-2 head-mean exchange (1 node/block)

    int widx = threadIdx.x >> 5;
    int lane = threadIdx.x & 31;
    int gw = blockIdx.x * ((int)blockDim.x >> 5) + widx;
    int n = gw / WPN;
    int half = gw - n * WPN;
    int cbase = half * 256 + lane * 8;

    ull w2[16][4];
#pragma unroll
    for (int k = 0; k < 16; k++) {
        const ulonglong2* q = (const ulonglong2*)(We + k * HC + cbase);
        ulonglong2 u0 = q[0], u1 = q[1];
        w2[k][0] = u0.x; w2[k][1] = u0.y; w2[k][2] = u1.x; w2[k][3] = u1.y;
    }
    float att_r[8];
    {
        float4 a = *(const float4*)(att + cbase);
        float4 b = *(const float4*)(att + cbase + 4);
        att_r[0] = a.x; att_r[1] = a.y; att_r[2] = a.z; att_r[3] = a.w;
        att_r[4] = b.x; att_r[5] = b.y; att_r[6] = b.z; att_r[7] = b.w;
    }
    ull xr2[4];
    {
        const ulonglong2* q = (const ulonglong2*)(XR + (long)n * HC + cbase);
        ulonglong2 u0 = q[0], u1 = q[1];
        xr2[0] = u0.x; xr2[1] = u0.y; xr2[2] = u1.x; xr2[3] = u1.y;
    }

    int e0 = rowptr[n], e1 = rowptr[n + 1];
    float m = -3.0e38f, s = 0.f;
    ull acc2[4] = {0ULL, 0ULL, 0ULL, 0ULL};

    float4 cA, cB, cC, cD;
    if (e0 < e1) {
        const float4* q = (const float4*)(EACSR + (long)e0 * 16);
        cA = q[0]; cB = q[1]; cC = q[2]; cD = q[3];
    }

    for (int pb = e0; pb < e1; pb += 32) {
        int myp = pb + lane;
        int msrc = __ldg(&csrc[(myp < e1) ? myp : e1 - 1]);
        int cnt = min(32, e1 - pb);

        ulonglong2 cx0, cx1;
        {
            int s0 = __shfl_sync(FULLMASK, msrc, 0);
            const ulonglong2* xq = (const ulonglong2*)(XL + (long)s0 * HC + cbase);
            cx0 = xq[0]; cx1 = xq[1];
        }
        for (int i = 0; i < cnt; i++) {
            float4 uA = cA, uB = cB, uC = cC, uD = cD;
            ulonglong2 ux0 = cx0, ux1 = cx1;
            if (pb + i + 1 < e1) {
                const float4* q = (const float4*)(EACSR + (long)(pb + i + 1) * 16);
                cA = q[0]; cB = q[1]; cC = q[2]; cD = q[3];
            }
            if (i + 1 < cnt) {
                int sn = __shfl_sync(FULLMASK, msrc, i + 1);
                const ulonglong2* xq = (const ulonglong2*)(XL + (long)sn * HC + cbase);
                cx0 = xq[0]; cx1 = xq[1];
            }
            float ea[16] = {uA.x, uA.y, uA.z, uA.w, uB.x, uB.y, uB.z, uB.w,
                            uC.x, uC.y, uC.z, uC.w, uD.x, uD.y, uD.z, uD.w};
            ull xl2[4] = {ux0.x, ux0.y, ux1.x, ux1.y};

            ull v0 = add2(xl2[0], xr2[0]);
            ull v1 = add2(xl2[1], xr2[1]);
            ull v2 = add2(xl2[2], xr2[2]);
            ull v3 = add2(xl2[3], xr2[3]);
#pragma unroll
            for (int k = 0; k < 16; k++) {
                ull ak = dup2(ea[k]);
                fma2(v0, ak, w2[k][0]);
                fma2(v1, ak, w2[k][1]);
                fma2(v2, ak, w2[k][2]);
                fma2(v3, ak, w2[k][3]);
            }
            float f[8];
            unpack2(v0, f[0], f[1]); unpack2(v1, f[2], f[3]);
            unpack2(v2, f[4], f[5]); unpack2(v3, f[6], f[7]);
            float part = 0.f;
#pragma unroll
            for (int j = 0; j < 8; j++) {
                float vv = f[j];
                part = fmaf(att_r[j], fmaxf(vv, 0.2f * vv), part);
            }
#pragma unroll
            for (int off = 1; off < LPH; off <<= 1)
                part += __shfl_xor_sync(FULLMASK, part, off);

            if (part > m) {
                float sc = __expf(m - part);
                s *= sc;
                ull sc2 = dup2(sc);
#pragma unroll
                for (int j = 0; j < 4; j++) acc2[j] = mul2(acc2[j], sc2);
                m = part;
            }
            float pe = __expf(part - m);
            s += pe;
            ull pe2 = dup2(pe);
            fma2(acc2[0], pe2, xl2[0]);
            fma2(acc2[1], pe2, xl2[1]);
            fma2(acc2[2], pe2, xl2[2]);
            fma2(acc2[3], pe2, xl2[3]);
        }
    }

    float inv = (e1 > e0) ? (1.f / s) : 0.f;
    float r[8];
    unpack2(acc2[0], r[0], r[1]); unpack2(acc2[1], r[2], r[3]);
    unpack2(acc2[2], r[4], r[5]); unpack2(acc2[3], r[6], r[7]);

    if (CONCAT) {
        float4 b0 = *(const float4*)(bias + cbase);
        float4 b1 = *(const float4*)(bias + cbase + 4);
        float4 o0, o1;
        o0.x = fmaf(r[0], inv, b0.x); o0.y = fmaf(r[1], inv, b0.y);
        o0.z = fmaf(r[2], inv, b0.z); o0.w = fmaf(r[3], inv, b0.w);
        o1.x = fmaf(r[4], inv, b1.x); o1.y = fmaf(r[5], inv, b1.y);
        o1.z = fmaf(r[6], inv, b1.z); o1.w = fmaf(r[7], inv, b1.w);
        float* q = Hout + (long)n * HC + cbase;
        *(float4*)q = o0;
        *(float4*)(q + 4) = o1;
    } else {
        // mean over 4 heads: shfl 16 pairs the warp's 2 heads; the node's two
        // warps (same block) combine through shared memory.
#pragma unroll
        for (int j = 0; j < 8; j++) {
            r[j] *= inv;
            r[j] += __shfl_xor_sync(FULLMASK, r[j], 16);
        }
        int c = (lane & 15) * 8;
        if (half == 0 && lane < 16) {
#pragma unroll
            for (int j = 0; j < 8; j++) s_red[c + j] = r[j];
        }
        __syncthreads();
        if (half == 1 && lane < 16) {
            float* q = Hout + (long)n * C + c;
#pragma unroll
            for (int j = 0; j < 8; j++)
                q[j] = bias[c + j] + 0.25f * (r[j] + s_red[c + j]);
        }
    }
}

// ---------------- pooling ----------------------------------------------------
__global__ void k_pool_init(float* out, int* gcnt) {
    int i = blockIdx.x * blockDim.x + threadIdx.x;
    if (i < NG * 256) out[i] = ((i & 255) < 128) ? -FLT_MAX : 0.f;
    if (i < NG) gcnt[i] = 0;
}

__global__ void k_pool_acc(const float* __restrict__ H, const int* __restrict__ batch,
                           float* out, int* gcnt) {
    int i = blockIdx.x * blockDim.x + threadIdx.x;
    if (i >= NN * 128) return;
    int nd = i >> 7, c = i & 127;
    int g = batch[nd];
    float v = H[i];
    float* mx = out + g * 256 + c;
    if (v >= 0.f) atomicMax((int*)mx, __float_as_int(v));
    else atomicMin((unsigned int*)mx, __float_as_uint(v));
    atomicAdd(out + g * 256 + 128 + c, v);
    if (c == 0) atomicAdd(&gcnt[g], 1);
}

__global__ void k_pool_fin(float* out, const int* __restrict__ gcnt) {
    int i = blockIdx.x * blockDim.x + threadIdx.x;
    if (i < NG * 128) {
        int g = i >> 7, c = i & 127;
        float cnt = (float)(gcnt[g] > 0 ? gcnt[g] : 1);
        out[g * 256 + 128 + c] /= cnt;
    }
}

// ---------------- launch -----------------------------------------------------
extern "C" void kernel_launch(void* const* d_in, const int* in_sizes, int n_in,
                              void* d_out, int out_size)
{
    const float* x     = (const float*)d_in[0];
    const float* ea    = (const float*)d_in[1];
    const int*   ei    = (const int*)d_in[2];
    const int*   batch = (const int*)d_in[3];
    const float* Wl[3] = {(const float*)d_in[4],  (const float*)d_in[11], (const float*)d_in[18]};
    const float* bl[3] = {(const float*)d_in[5],  (const float*)d_in[12], (const float*)d_in[19]};
    const float* Wr[3] = {(const float*)d_in[6],  (const float*)d_in[13], (const float*)d_in[20]};
    const float* br[3] = {(const float*)d_in[7],  (const float*)d_in[14], (const float*)d_in[21]};
    const float* We[3] = {(const float*)d_in[8],  (const float*)d_in[15], (const float*)d_in[22]};
    const float* At[3] = {(const float*)d_in[9],  (const float*)d_in[16], (const float*)d_in[23]};
    const float* Bi[3] = {(const float*)d_in[10], (const float*)d_in[17], (const float*)d_in[24]};
    float* out = (float*)d_out;

    float *XL, *XR, *HA, *HB, *eacsr;
    int *cnt, *rowptr, *cursor, *csrc, *ceid, *gcnt;
    cudaGetSymbolAddress((void**)&XL, g_XL);
    cudaGetSymbolAddress((void**)&XR, g_XR);
    cudaGetSymbolAddress((void**)&HA, g_HA);
    cudaGetSymbolAddress((void**)&HB, g_HB);
    cudaGetSymbolAddress((void**)&cnt, g_cnt);
    cudaGetSymbolAddress((void**)&rowptr, g_rowptr);
    cudaGetSymbolAddress((void**)&cursor, g_cursor);
    cudaGetSymbolAddress((void**)&csrc, g_csrc);
    cudaGetSymbolAddress((void**)&ceid, g_ceid);
    cudaGetSymbolAddress((void**)&eacsr, g_eacsr);
    cudaGetSymbolAddress((void**)&gcnt, g_gcnt);

    const int MT = (NN + 127) / 128;  // 157

    // ---- CSR histogram + scan (launches 1-3) ----
    k_zero_cnt<<<(NN + 255) / 256, 256>>>(cnt, NN);
    k_hist<<<(NE + 255) / 256, 256>>>(ei, cnt, NE);
    k_scan<<<1, 1024>>>(cnt, rowptr, cursor, NN);

    // ---- launch 4 = ncu capture slot: first GEMM ----
    k_gemm_bias<<<dim3(4, MT), 256>>>(x, Wl[0], bl[0], XL, NN, 256, 128);
    k_gemm_bias<<<dim3(4, MT), 256>>>(x, Wr[0], br[0], XR, NN, 256, 128);

    // ---- finish CSR ----
    k_scatter<<<(NE + 255) / 256, 256>>>(ei, cursor, csrc, ceid, NE);
    k_gather_ea<<<(NE + 255) / 256, 256>>>(ea, ceid, eacsr, NE);

    // ---- layer 0 attention: one 32-thread block per node ----
    k_gat<256, 64, true><<<NN, 32>>>(XL, XR, eacsr, At[0], Bi[0], We[0],
                                     rowptr, csrc, HA, NN);

    // ---- layer 1 ----
    k_gemm_bias<<<dim3(4, MT), 256>>>(HA, Wl[1], bl[1], XL, NN, 256, 256);
    k_gemm_bias<<<dim3(4, MT), 256>>>(HA, Wr[1], br[1], XR, NN, 256, 256);
    k_gat<256, 64, true><<<NN, 32>>>(XL, XR, eacsr, At[1], Bi[1], We[1],
                                     rowptr, csrc, HB, NN);

    // ---- layer 2 (mean over heads): one 64-thread block per node ----
    k_gemm_bias<<<dim3(8, MT), 256>>>(HB, Wl[2], bl[2], XL, NN, 512, 256);
    k_gemm_bias<<<dim3(8, MT), 256>>>(HB, Wr[2], br[2], XR, NN, 512, 256);
    k_gat<512, 128, false><<<NN, 64>>>(XL, XR, eacsr, At[2], Bi[2], We[2],
                                       rowptr, csrc, HA, NN);

    // ---- pooling ----
    k_pool_init<<<64, 256>>>(out, gcnt);
    k_pool_acc<<<(NN * 128 + 255) / 256, 256>>>(HA, batch, out, gcnt);
    k_pool_fin<<<32, 256>>>(out, gcnt);
}